// round 8
// baseline (speedup 1.0000x reference)
#include <cuda_runtime.h>
#include <math.h>

#define N_LEVELS      16
#define HASHMAP_SIZE  (1u << 19)
#define HASH_MASK     (HASHMAP_SIZE - 1u)
#define P2            2654435761u
#define P3            805459861u

#define KEY_BITS_AXIS 6
#define HISTO_SIZE    (1u << (3 * KEY_BITS_AXIS))   // 2^18 buckets
#define SCAN_BLOCKS   (HISTO_SIZE / 1024)           // 256
#define MAX_POINTS    2200000

struct ResTable {
    int res[N_LEVELS];
};

// ---- static scratch (no dynamic allocation allowed) ----
__device__ unsigned g_histo[HISTO_SIZE];   // counts -> excl-within-block -> cursors
__device__ unsigned g_bsum[SCAN_BLOCKS];   // exclusive block offsets
__device__ unsigned g_keys[MAX_POINTS];
__device__ float4   g_spos[MAX_POINTS];    // sorted (x, y, z, orig_idx)

// ---------------- sort pre-pass ----------------

__device__ __forceinline__ unsigned part1by2(unsigned x) {
    x &= 0x3ff;
    x = (x | (x << 16)) & 0x030000FF;
    x = (x | (x << 8))  & 0x0300F00F;
    x = (x | (x << 4))  & 0x030C30C3;
    x = (x | (x << 2))  & 0x09249249;
    return x;
}

__global__ void k_key_histo(const float* __restrict__ pos, int n) {
    int i = blockIdx.x * blockDim.x + threadIdx.x;
    if (i >= n) return;
    const int R = 1 << KEY_BITS_AXIS;
    unsigned kx = min(R - 1, max(0, (int)(pos[i * 3 + 0] * (float)R)));
    unsigned ky = min(R - 1, max(0, (int)(pos[i * 3 + 1] * (float)R)));
    unsigned kz = min(R - 1, max(0, (int)(pos[i * 3 + 2] * (float)R)));
    unsigned key = part1by2(kx) | (part1by2(ky) << 1) | (part1by2(kz) << 2);
    g_keys[i] = key;
    atomicAdd(&g_histo[key], 1u);
}

// Per-1024-bucket exclusive scan (warp-shuffle based).
__global__ void k_scan1() {
    __shared__ unsigned wsum[32];
    const unsigned t    = threadIdx.x;
    const unsigned lane = t & 31;
    const unsigned warp = t >> 5;
    const unsigned i    = blockIdx.x * 1024 + t;

    const unsigned v = g_histo[i];
    // warp inclusive scan
    unsigned s = v;
#pragma unroll
    for (int o = 1; o < 32; o <<= 1) {
        unsigned u = __shfl_up_sync(0xffffffffu, s, o);
        if (lane >= (unsigned)o) s += u;
    }
    if (lane == 31) wsum[warp] = s;
    __syncthreads();
    if (warp == 0) {
        unsigned w = wsum[lane];
#pragma unroll
        for (int o = 1; o < 32; o <<= 1) {
            unsigned u = __shfl_up_sync(0xffffffffu, w, o);
            if (lane >= (unsigned)o) w += u;
        }
        wsum[lane] = w;   // inclusive warp totals
    }
    __syncthreads();
    const unsigned base = (warp == 0) ? 0u : wsum[warp - 1];
    g_histo[i] = base + s - v;                       // exclusive within block
    if (t == 1023) g_bsum[blockIdx.x] = base + s;    // block total
}

// Exclusive scan of the 256 block totals (one block).
__global__ void k_scan2() {
    __shared__ unsigned wsum[8];
    const unsigned t    = threadIdx.x;    // 256 threads
    const unsigned lane = t & 31;
    const unsigned warp = t >> 5;
    const unsigned v = g_bsum[t];
    unsigned s = v;
#pragma unroll
    for (int o = 1; o < 32; o <<= 1) {
        unsigned u = __shfl_up_sync(0xffffffffu, s, o);
        if (lane >= (unsigned)o) s += u;
    }
    if (lane == 31) wsum[warp] = s;
    __syncthreads();
    if (t < 8) {
        unsigned w = wsum[t];
#pragma unroll
        for (int o = 1; o < 8; o <<= 1) {
            unsigned u = __shfl_up_sync(0xffu, w, o);
            if (t >= (unsigned)o) w += u;
        }
        wsum[t] = w;
    }
    __syncthreads();
    const unsigned base = (warp == 0) ? 0u : wsum[warp - 1];
    g_bsum[t] = base + s - v;                        // exclusive block offset
}

__global__ void k_scatter(const float* __restrict__ pos, int n) {
    int i = blockIdx.x * blockDim.x + threadIdx.x;
    if (i >= n) return;
    const unsigned key = g_keys[i];
    const unsigned dst = g_bsum[key >> 10] + atomicAdd(&g_histo[key], 1u);
    g_spos[dst] = make_float4(pos[i * 3 + 0], pos[i * 3 + 1], pos[i * 3 + 2],
                              __int_as_float(i));
}

// ---------------- main encode (R5 body, sorted input) ----------------

__global__ void __launch_bounds__(256)
hashenc_kernel(const float* __restrict__ emb,
               float* __restrict__ out,
               ResTable rt,
               int n_points)
{
    const int tid   = blockIdx.x * blockDim.x + threadIdx.x;
    const int lane  = threadIdx.x & 31;
    const int c     = lane & 7;
    const int sub   = lane >> 3;
    const int pslot = (tid >> 5) * 4 + sub;

    const bool valid = (pslot < n_points);
    const int  ps    = valid ? pslot : 0;

    const unsigned bi = (c >> 2) & 1;
    const unsigned bj = (c >> 1) & 1;
    const unsigned bk =  c       & 1;

    const float4 sp = __ldg(&g_spos[ps]);
    const float px = sp.x, py = sp.y, pz = sp.z;
    const int orig = __float_as_int(sp.w);

    float acc0 = 0.f, acc1 = 0.f, acc2 = 0.f, acc3 = 0.f;

#pragma unroll
    for (int l = 0; l < N_LEVELS; ++l) {
        const int   res  = rt.res[l];
        const float fres = (float)res;

        const float sx = px * fres, sy = py * fres, sz = pz * fres;
        const float fx = floorf(sx), fy = floorf(sy), fz = floorf(sz);
        const float wx = sx - fx,   wy = sy - fy,   wz = sz - fz;

        const unsigned ux = (unsigned)(int)fx + bi;
        const unsigned uy = (unsigned)(int)fy + bj;
        const unsigned uz = (unsigned)(int)fz + bk;

        const unsigned r1 = (unsigned)(res + 1);
        const bool dense =
            ((long long)r1 * (long long)r1 * (long long)r1) <= (long long)HASHMAP_SIZE;

        unsigned idx;
        if (dense) {
            idx = ux * (r1 * r1) + uy * r1 + uz;
        } else {
            idx = (ux ^ (uy * P2) ^ (uz * P3)) & HASH_MASK;
        }

        const float2* __restrict__ table =
            reinterpret_cast<const float2*>(emb) + (size_t)l * HASHMAP_SIZE;
        const float2 f = __ldg(&table[idx]);

        const float ax = bi ? wx : (1.0f - wx);
        const float ay = bj ? wy : (1.0f - wy);
        const float az = bk ? wz : (1.0f - wz);
        const float w  = ax * ay * az;

        float v0 = f.x * w;
        float v1 = f.y * w;

        v0 += __shfl_xor_sync(0xffffffffu, v0, 4);
        v1 += __shfl_xor_sync(0xffffffffu, v1, 4);
        v0 += __shfl_xor_sync(0xffffffffu, v0, 2);
        v1 += __shfl_xor_sync(0xffffffffu, v1, 2);
        v0 += __shfl_xor_sync(0xffffffffu, v0, 1);
        v1 += __shfl_xor_sync(0xffffffffu, v1, 1);

        if ((l >> 1) == c) {
            if (l & 1) { acc2 = v0; acc3 = v1; }
            else       { acc0 = v0; acc1 = v1; }
        }
    }

    if (valid) {
        float4* __restrict__ o4 = reinterpret_cast<float4*>(out);
        o4[(size_t)orig * 8 + c] = make_float4(acc0, acc1, acc2, acc3);
    }
}

extern "C" void kernel_launch(void* const* d_in, const int* in_sizes, int n_in,
                              void* d_out, int out_size)
{
    const float* positions  = (const float*)d_in[0];   // [N_POINTS, 3] f32
    const float* embeddings = (const float*)d_in[1];   // [16, 2^19, 2] f32
    float*       out        = (float*)d_out;           // [N_POINTS, 32] f32

    const int n_points = in_sizes[0] / 3;

    ResTable rt;
    const double scale = exp((log(2048.0) - log(16.0)) / 15.0);
    for (int l = 0; l < N_LEVELS; ++l) {
        rt.res[l] = (int)floor(16.0 * pow(scale, (double)l));
    }

    // ---- sort pre-pass ----
    void* histo_ptr = nullptr;
    cudaGetSymbolAddress(&histo_ptr, g_histo);
    cudaMemsetAsync(histo_ptr, 0, HISTO_SIZE * sizeof(unsigned));

    const int pblocks = (n_points + 255) / 256;
    k_key_histo<<<pblocks, 256>>>(positions, n_points);
    k_scan1<<<SCAN_BLOCKS, 1024>>>();
    k_scan2<<<1, 256>>>();
    k_scatter<<<pblocks, 256>>>(positions, n_points);

    // ---- main encode: 8 threads per point ----
    const long long total_threads = (long long)n_points * 8;
    const int threads = 256;
    const int blocks  = (int)((total_threads + threads - 1) / threads);
    hashenc_kernel<<<blocks, threads>>>(embeddings, out, rt, n_points);
}